// round 16
// baseline (speedup 1.0000x reference)
#include <cuda_runtime.h>
#include <cuda_bf16.h>

// KBpA via field precompute + bicubic interpolation.
//   F(x,y) = sum_ij alphas[i,j] exp(-((x-4i-2)^2+(y-4j-2)^2)/50)  (b-indep!)
// K1: F on a 160x160 unit grid (origin -16), 11x12 truncated separable dot.
// K2: per pixel, deformation (separable 21x21 conv) then bicubic interp of F.

#define KCC  0.52729242f    // exp(-0.64)

__device__ float gF[160 * 160];   // precomputed field (static scratch)

static __device__ __forceinline__ unsigned long long pk2(float lo, float hi) {
    unsigned long long r;
    asm("mov.b64 %0, {%1, %2};" : "=l"(r) : "f"(lo), "f"(hi));
    return r;
}
static __device__ __forceinline__ float2 unpk2(unsigned long long v) {
    float2 r;
    asm("mov.b64 {%0, %1}, %2;" : "=f"(r.x), "=f"(r.y) : "l"(v));
    return r;
}
static __device__ __forceinline__ void fma2(unsigned long long& d,
                                            unsigned long long a,
                                            unsigned long long b) {
    asm("fma.rn.f32x2 %0, %1, %2, %0;" : "+l"(d) : "l"(a), "l"(b));
}
static __device__ __forceinline__ void mul2o(unsigned long long& d,
                                             unsigned long long a,
                                             unsigned long long b) {
    asm("mul.rn.f32x2 %0, %1, %2;" : "=l"(d) : "l"(a), "l"(b));
}
static __device__ __forceinline__ void mul2(unsigned long long& d,
                                            unsigned long long a) {
    asm("mul.rn.f32x2 %0, %0, %1;" : "+l"(d) : "l"(a));
}

// ---------------- K1: field precompute --------------------------------
__global__ __launch_bounds__(160) void field_kernel(
    const float* __restrict__ alphas)      // (1024,)
{
    __shared__ __align__(16) float sAk[11][52];   // rows i0..i0+10, cols -10..41

    const int gx = blockIdx.x;            // F row (x = gx - 16), const per block
    const int gy = threadIdx.x;           // F col (y = gy - 16)
    const float x = (float)(gx - 16);
    const float y = (float)(gy - 16);

    const int im = __float2int_rn((x - 2.f) * 0.25f);
    const int i0 = im - 5;                               // 11-row window

    for (int idx = gy; idx < 11 * 52; idx += 160) {
        const int rl = idx / 52, clq = idx - rl * 52;
        const int i = i0 + rl, j = clq - 10;
        float v = 0.f;
        if ((unsigned)i < 32u && (unsigned)j < 32u) v = alphas[(i << 5) + j];
        sAk[rl][clq] = v;
    }
    __syncthreads();

    const int jm = __float2int_rn((y - 2.f) * 0.25f);
    const int j0 = (jm - 5) & ~1;                        // 2-aligned 12 cols

    // ey[12] via exp-ratio chain, packed
    const float dy = y - (float)(4 * j0 + 2);
    float ea = __expf(dy * dy * -0.02f);
    float ra = __expf(0.16f * dy - 0.32f);
    float ev[12];
    ev[0] = ea;
#pragma unroll
    for (int l = 1; l < 12; ++l) { ea *= ra; ra *= KCC; ev[l] = ea; }
    unsigned long long eyp[6];
#pragma unroll
    for (int l = 0; l < 6; ++l) eyp[l] = pk2(ev[2 * l], ev[2 * l + 1]);

    const float dx = x - (float)(4 * i0 + 2);
    const float e0 = __expf(dx * dx * -0.02f);
    const float r0f = __expf(0.16f * dx - 0.32f);
    unsigned long long ee2 = pk2(e0, e0);
    unsigned long long er2 = pk2(r0f, r0f);
    unsigned long long acc2 = 0ull;
    const unsigned long long kcc2 = pk2(KCC, KCC);

    const float* Arow = &sAk[0][j0 + 10];
#pragma unroll
    for (int k = 0; k < 11; ++k) {
        const unsigned long long* src = (const unsigned long long*)Arow;
        unsigned long long s2;
        mul2o(s2, src[0], eyp[0]);
        fma2(s2, src[1], eyp[1]);
        fma2(s2, src[2], eyp[2]);
        fma2(s2, src[3], eyp[3]);
        fma2(s2, src[4], eyp[4]);
        fma2(s2, src[5], eyp[5]);
        fma2(acc2, s2, ee2);
        mul2(ee2, er2);
        mul2(er2, kcc2);
        Arow += 52;
    }
    const float2 v = unpk2(acc2);
    gF[gx * 160 + gy] = v.x + v.y;
}

// ---------------- K2: deformation + bicubic interp --------------------
#define TPB 256

static __device__ __forceinline__ void cubw(float t, float w[4]) {
    const float tm1 = t - 1.f, tm2 = t - 2.f, tp1 = t + 1.f;
    const float a = t * tm1, bq = tp1 * tm2;
    w[0] = a * tm2 * (-1.f / 6.f);
    w[1] = bq * tm1 * 0.5f;
    w[2] = bq * t * (-0.5f);
    w[3] = a * tp1 * (1.f / 6.f);
}

__global__ __launch_bounds__(TPB) void interp_kernel(
    const float* __restrict__ betas,   // (16, 1024, 2)
    const float* __restrict__ kern,    // (21, 21)  (separable: g g^T)
    float* __restrict__ out)           // (16, 16384)
{
    __shared__ float sF[35 * 51];                     // F tile + cubic halo
    __shared__ float sB[2][10][16];                   // local betas window
    __shared__ __align__(16) float sT[2][10][32];     // deformation col-pass
    __shared__ float sG[4][8];                        // 1D conv taps per phase

    const int b  = blockIdx.y;
    const int r0 = (blockIdx.x >> 2) << 4;   // 8 row-tiles of 16
    const int c0 = (blockIdx.x & 3)  << 5;   // 4 col-tiles of 32
    const int tid = threadIdx.x;

    const int gibase = (r0 >> 2) - 2;
    const int gjbase = (c0 >> 2) - 2;

    // ---- fills ----
    // sF: F rows r0+7..r0+41, cols c0+7..c0+57 (F coord = pixel + 16)
    {
        const float* src = &gF[(r0 + 7) * 160 + (c0 + 7)];
        for (int idx = tid; idx < 35 * 51; idx += TPB) {
            const int ri = idx / 51, ci = idx - ri * 51;
            sF[idx] = src[ri * 160 + ci];
        }
    }
    for (int idx = tid; idx < 160; idx += TPB) {
        const int rl = idx >> 4, clc = idx & 15;
        const int gi = gibase + rl, gj = gjbase + clc;
        float v0 = 0.f, v1 = 0.f;
        if ((unsigned)gi < 32u && (unsigned)gj < 32u) {
            const int m = (((b << 5) + gi) << 5) + gj;
            v0 = betas[2 * m];
            v1 = betas[2 * m + 1];
        }
        sB[0][rl][clc] = v0;
        sB[1][rl][clc] = v1;
    }
    if (tid < 24) {
        const int s = tid / 6, k = tid - s * 6;
        const int dc0 = (s == 3) ? 7 : (8 + s);
        const int dc = dc0 - 4 * k;
        sG[s][k] = (dc >= -10 && dc <= 10) ? kern[(dc + 10) * 21 + 10] : 0.f;
    }
    __syncthreads();

    // ---- deformation column pass ----
    for (int idx = tid; idx < 320; idx += TPB) {
        const int giloc = idx >> 5, cloc = idx & 31;
        const int c = c0 + cloc;
        const int s = c & 3;
        const int gjl = (c >> 2) - (c0 >> 2) + (s == 3);
        float t0 = 0.f, t1 = 0.f;
#pragma unroll
        for (int l = 0; l < 6; ++l) {
            const float w = sG[s][l];
            t0 = fmaf(w, sB[0][giloc][gjl + l], t0);
            t1 = fmaf(w, sB[1][giloc][gjl + l], t1);
        }
        sT[0][giloc][cloc] = t0;
        sT[1][giloc][cloc] = t1;
    }
    __syncthreads();

    // ---- per-thread pair of pixels ----
    const int rr = r0 + (tid >> 4);
    const int cb = c0 + ((tid & 15) << 1);
    const int sr = rr & 3;
    const int g0 = (rr >> 2) - (r0 >> 2) + (sr == 3);
    const int cl = cb - c0;

    float2 d0 = make_float2(0.f, 0.f), d1 = d0;
#pragma unroll
    for (int k = 0; k < 6; ++k) {
        const float w = sG[sr][k];
        const float2 t0 = *(const float2*)&sT[0][g0 + k][cl];
        const float2 t1 = *(const float2*)&sT[1][g0 + k][cl];
        d0.x = fmaf(w, t0.x, d0.x); d0.y = fmaf(w, t0.y, d0.y);
        d1.x = fmaf(w, t1.x, d1.x); d1.y = fmaf(w, t1.y, d1.y);
    }
    const float xsv[2] = {(float)rr - d0.x, (float)rr - d0.y};
    const float ysv[2] = {(float)cb - d1.x, (float)(cb + 1) - d1.y};

    float res[2];
#pragma unroll
    for (int p = 0; p < 2; ++p) {
        // sF row 0 = pixel coord r0-9; col 0 = pixel coord c0-9
        const float fx = xsv[p] - (float)(r0 - 9);
        const float fy = ysv[p] - (float)(c0 - 9);
        const float fxf = floorf(fx), fyf = floorf(fy);
        int irx = (int)fxf, iry = (int)fyf;
        const float tx = fx - fxf, ty = fy - fyf;
        irx = min(max(irx, 1), 32);
        iry = min(max(iry, 1), 48);

        float wx[4], wy[4];
        cubw(tx, wx);
        cubw(ty, wy);

        const float* rp = &sF[(irx - 1) * 51 + (iry - 1)];
        float s = 0.f;
#pragma unroll
        for (int a = 0; a < 4; ++a) {
            float rv = rp[0] * wy[0];
            rv = fmaf(rp[1], wy[1], rv);
            rv = fmaf(rp[2], wy[2], rv);
            rv = fmaf(rp[3], wy[3], rv);
            s = fmaf(wx[a], rv, s);
            rp += 51;
        }
        res[p] = s;
    }

    *(float2*)&out[(b << 14) + (rr << 7) + cb] = make_float2(res[0], res[1]);
}

extern "C" void kernel_launch(void* const* d_in, const int* in_sizes, int n_in,
                              void* d_out, int out_size) {
    const float* betas  = (const float*)d_in[0];
    const float* alphas = (const float*)d_in[1];
    const float* kern   = (const float*)d_in[2];
    float* out = (float*)d_out;

    field_kernel<<<160, 160>>>(alphas);
    dim3 grid(32, 16);   // 8x4 tiles of 16x32 pixels, 16 batches
    interp_kernel<<<grid, TPB>>>(betas, kern, out);
}

// round 17
// speedup vs baseline: 1.3409x; 1.3409x over previous
#include <cuda_runtime.h>
#include <cuda_bf16.h>

// KBpA via batch-independent field precompute + bicubic interpolation.
//   F(x,y) = sum_ij alphas[i,j] exp(-((x-4i-2)^2+(y-4j-2)^2)/50)
// K1: F on a 160x160 unit grid (origin -16), 11x12 truncated separable dot.
// K2: deformation (separable 21x21 conv) + bicubic interp of F using
//     overlapping-pair packed smem (2 aligned LDS.64 per tap row).

#define KCC  0.52729242f    // exp(-0.64)

__device__ float gF[160 * 160];   // precomputed field (static scratch)

static __device__ __forceinline__ unsigned long long pk2(float lo, float hi) {
    unsigned long long r;
    asm("mov.b64 %0, {%1, %2};" : "=l"(r) : "f"(lo), "f"(hi));
    return r;
}
static __device__ __forceinline__ float2 unpk2(unsigned long long v) {
    float2 r;
    asm("mov.b64 {%0, %1}, %2;" : "=f"(r.x), "=f"(r.y) : "l"(v));
    return r;
}
static __device__ __forceinline__ void fma2(unsigned long long& d,
                                            unsigned long long a,
                                            unsigned long long b) {
    asm("fma.rn.f32x2 %0, %1, %2, %0;" : "+l"(d) : "l"(a), "l"(b));
}
static __device__ __forceinline__ void mul2o(unsigned long long& d,
                                             unsigned long long a,
                                             unsigned long long b) {
    asm("mul.rn.f32x2 %0, %1, %2;" : "=l"(d) : "l"(a), "l"(b));
}
static __device__ __forceinline__ void mul2(unsigned long long& d,
                                            unsigned long long a) {
    asm("mul.rn.f32x2 %0, %0, %1;" : "+l"(d) : "l"(a));
}

// ---------------- K1: field precompute (1 point/thread) ----------------
__global__ __launch_bounds__(256) void field_kernel(
    const float* __restrict__ alphas)      // (1024,)
{
    // zero-padded alphas: row = i+9 (i in -9..40), col = j+10 (j in -10..41)
    __shared__ __align__(16) float sAf[50 * 52];

    const int tid = threadIdx.x;
    for (int idx = tid; idx < 50 * 52; idx += 256) {
        const int rl = idx / 52, clq = idx - rl * 52;
        const int i = rl - 9, j = clq - 10;
        float v = 0.f;
        if ((unsigned)i < 32u && (unsigned)j < 32u) v = alphas[(i << 5) + j];
        sAf[idx] = v;
    }
    __syncthreads();

    const int id = blockIdx.x * 256 + tid;     // < 25600
    const int gx = id / 160, gy = id - 160 * (id / 160);
    const float x = (float)(gx - 16);
    const float y = (float)(gy - 16);

    const int im = __float2int_rn((x - 2.f) * 0.25f);
    const int jm = __float2int_rn((y - 2.f) * 0.25f);
    const int i0 = im - 5;                     // 11-row window
    const int j0 = (jm - 5) & ~1;              // 2-aligned 12-col window

    // ey[12] via exp-ratio chain, packed
    const float dy = y - (float)(4 * j0 + 2);
    float ea = __expf(dy * dy * -0.02f);
    float ra = __expf(0.16f * dy - 0.32f);
    float ev[12];
    ev[0] = ea;
#pragma unroll
    for (int l = 1; l < 12; ++l) { ea *= ra; ra *= KCC; ev[l] = ea; }
    unsigned long long eyp[6];
#pragma unroll
    for (int l = 0; l < 6; ++l) eyp[l] = pk2(ev[2 * l], ev[2 * l + 1]);

    const float dx = x - (float)(4 * i0 + 2);
    const float e0 = __expf(dx * dx * -0.02f);
    const float r0f = __expf(0.16f * dx - 0.32f);
    unsigned long long ee2 = pk2(e0, e0);
    unsigned long long er2 = pk2(r0f, r0f);
    unsigned long long acc2 = 0ull;
    const unsigned long long kcc2 = pk2(KCC, KCC);

    const float* Arow = &sAf[(i0 + 9) * 52 + (j0 + 10)];
#pragma unroll
    for (int k = 0; k < 11; ++k) {
        const unsigned long long* src = (const unsigned long long*)Arow;
        unsigned long long s2;
        mul2o(s2, src[0], eyp[0]);
        fma2(s2, src[1], eyp[1]);
        fma2(s2, src[2], eyp[2]);
        fma2(s2, src[3], eyp[3]);
        fma2(s2, src[4], eyp[4]);
        fma2(s2, src[5], eyp[5]);
        fma2(acc2, s2, ee2);
        mul2(ee2, er2);
        mul2(er2, kcc2);
        Arow += 52;
    }
    const float2 v = unpk2(acc2);
    gF[id] = v.x + v.y;
}

// ---------------- K2: deformation + packed bicubic interp --------------
#define TPB 256

static __device__ __forceinline__ void cubw(float t, float w[4]) {
    const float tm1 = t - 1.f, tm2 = t - 2.f, tp1 = t + 1.f;
    const float a = t * tm1, bq = tp1 * tm2;
    w[0] = a * tm2 * (-1.f / 6.f);
    w[1] = bq * tm1 * 0.5f;
    w[2] = bq * t * (-0.5f);
    w[3] = a * tp1 * (1.f / 6.f);
}

__global__ __launch_bounds__(TPB, 6) void interp_kernel(
    const float* __restrict__ betas,   // (16, 1024, 2)
    const float* __restrict__ kern,    // (21, 21)  (separable: g g^T)
    float* __restrict__ out)           // (16, 16384)
{
    __shared__ float sF[35 * 35];                     // F tile + cubic halo
    __shared__ __align__(16) unsigned long long sP[35 * 34];  // pair copies
    __shared__ float sB[2][10][12];                   // local betas window
    __shared__ __align__(16) float sT[2][10][16];     // deformation col-pass
    __shared__ float sG[4][8];                        // 1D conv taps per phase

    const int b  = blockIdx.y;
    const int r0 = (blockIdx.x >> 3) << 4;
    const int c0 = (blockIdx.x & 7)  << 4;
    const int tid = threadIdx.x;

    const int gibase = (r0 >> 2) - 2;
    const int gjbase = (c0 >> 2) - 2;

    // ---- fills ----
    // sF rows = pixels r0-9..r0+25 (gF row = pixel+16), cols c0-9..c0+25
    {
        const float* src = &gF[(r0 + 7) * 160 + (c0 + 7)];
        for (int idx = tid; idx < 35 * 35; idx += TPB) {
            const int ri = idx / 35, ci = idx - ri * 35;
            sF[idx] = src[ri * 160 + ci];
        }
    }
    for (int idx = tid; idx < 100; idx += TPB) {
        const int rl = idx / 10, clc = idx - rl * 10;
        const int gi = gibase + rl, gj = gjbase + clc;
        float v0 = 0.f, v1 = 0.f;
        if ((unsigned)gi < 32u && (unsigned)gj < 32u) {
            const int m = (((b << 5) + gi) << 5) + gj;
            v0 = betas[2 * m];
            v1 = betas[2 * m + 1];
        }
        sB[0][rl][clc] = v0;
        sB[1][rl][clc] = v1;
    }
    if (tid < 24) {
        const int s = tid / 6, k = tid - s * 6;
        const int dc0 = (s == 3) ? 7 : (8 + s);
        const int dc = dc0 - 4 * k;
        sG[s][k] = (dc >= -10 && dc <= 10) ? kern[(dc + 10) * 21 + 10] : 0.f;
    }
    __syncthreads();

    // ---- build overlapping-pair table + deformation column pass ----
    for (int idx = tid; idx < 35 * 34; idx += TPB) {
        const int ri = idx / 34, ci = idx - ri * 34;
        sP[idx] = pk2(sF[ri * 35 + ci], sF[ri * 35 + ci + 1]);
    }
    for (int idx = tid; idx < 160; idx += TPB) {
        const int giloc = idx >> 4, cloc = idx & 15;
        const int c = c0 + cloc;
        const int s = c & 3;
        const int gjl = (c >> 2) - (c0 >> 2) + (s == 3);
        float t0 = 0.f, t1 = 0.f;
#pragma unroll
        for (int l = 0; l < 6; ++l) {
            const float w = sG[s][l];
            t0 = fmaf(w, sB[0][giloc][gjl + l], t0);
            t1 = fmaf(w, sB[1][giloc][gjl + l], t1);
        }
        sT[0][giloc][cloc] = t0;
        sT[1][giloc][cloc] = t1;
    }
    __syncthreads();

    // ---- one pixel per thread ----
    const int rr = r0 + (tid >> 4);
    const int cc = c0 + (tid & 15);
    const int sr = rr & 3;
    const int g0 = (rr >> 2) - (r0 >> 2) + (sr == 3);
    const int cl = cc - c0;

    float def0 = 0.f, def1 = 0.f;
#pragma unroll
    for (int k = 0; k < 6; ++k) {
        const float w = sG[sr][k];
        def0 = fmaf(w, sT[0][g0 + k][cl], def0);
        def1 = fmaf(w, sT[1][g0 + k][cl], def1);
    }
    const float xs = (float)rr - def0;
    const float ys = (float)cc - def1;

    // bicubic: sF origin = pixel (r0-9, c0-9)
    const float fx = xs - (float)(r0 - 9);
    const float fy = ys - (float)(c0 - 9);
    const float fxf = floorf(fx), fyf = floorf(fy);
    int irx = (int)fxf, iry = (int)fyf;
    const float tx = fx - fxf, ty = fy - fyf;
    irx = min(max(irx, 1), 32);
    iry = min(max(iry, 1), 32);

    float wx[4], wy[4];
    cubw(tx, wx);
    cubw(ty, wy);

    const unsigned long long wyp01 = pk2(wy[0], wy[1]);
    const unsigned long long wyp23 = pk2(wy[2], wy[3]);

    const unsigned long long* rp = &sP[(irx - 1) * 34 + (iry - 1)];
    unsigned long long acc2 = 0ull;
#pragma unroll
    for (int a = 0; a < 4; ++a) {
        unsigned long long s2;
        mul2o(s2, rp[0], wyp01);          // taps y-1, y
        fma2(s2, rp[2], wyp23);           // taps y+1, y+2
        fma2(acc2, s2, pk2(wx[a], wx[a]));
        rp += 34;
    }
    const float2 v = unpk2(acc2);
    out[(b << 14) + (rr << 7) + cc] = v.x + v.y;
}

extern "C" void kernel_launch(void* const* d_in, const int* in_sizes, int n_in,
                              void* d_out, int out_size) {
    const float* betas  = (const float*)d_in[0];
    const float* alphas = (const float*)d_in[1];
    const float* kern   = (const float*)d_in[2];
    float* out = (float*)d_out;

    field_kernel<<<100, 256>>>(alphas);
    dim3 grid(64, 16);   // 8x8 tiles of 16x16 pixels, 16 batches
    interp_kernel<<<grid, TPB>>>(betas, kern, out);
}